// round 3
// baseline (speedup 1.0000x reference)
#include <cuda_runtime.h>
#include <cstdint>

// Problem constants
#define NT       65536     // tokens = 16*4096
#define D        64        // feature dim
#define C        2048      // codes
#define TPB_TOK  128       // tokens per block tile
#define CT       64        // codes per smem tile
#define NTILES   (C / CT)  // 32
#define ES_STRIDE 68       // padded row stride (floats) for code tile; 68*4=272 B, 16B-aligned

// Output layout (concatenated fp32, reference return order):
// quantize (4194304) | embed_ind (65536) | new_embeddings (131072) |
// new_cluster_size (2048) | new_embed_avg (131072)
#define OFF_IND  4194304
#define OFF_EMB  4259840
#define OFF_CS   4390912
#define OFF_EA   4392960

#define DECAY    0.8f
#define EPSV     1e-5f

// Scratch (no cudaMalloc allowed)
__device__ float g_embed_sum[C * D];
__device__ float g_counts[C];
__device__ float g_e2[C];
__device__ float g_smooth[C];

// ---------------- helpers ----------------
__device__ __forceinline__ void cp_async16(void* smem_dst, const void* gmem_src) {
    uint32_t s = (uint32_t)__cvta_generic_to_shared(smem_dst);
    asm volatile("cp.async.cg.shared.global [%0], [%1], 16;\n" :: "r"(s), "l"(gmem_src));
}
__device__ __forceinline__ void cp_commit() {
    asm volatile("cp.async.commit_group;\n" ::: "memory");
}
__device__ __forceinline__ void fma2(unsigned long long& acc, unsigned long long a, unsigned long long b) {
    asm("fma.rn.f32x2 %0, %1, %2, %0;" : "+l"(acc) : "l"(a), "l"(b));
}

// ---------------- K0: zero scatter scratch ----------------
__global__ void k_zero() {
    int i = blockIdx.x * 256 + threadIdx.x;
    if (i < C * D) g_embed_sum[i] = 0.0f;
    if (i < C)     g_counts[i]    = 0.0f;
}

// ---------------- K1: per-code squared norms ----------------
__global__ void k_e2(const float* __restrict__ emb) {
    int c = blockIdx.x * 256 + threadIdx.x;
    if (c < C) {
        const float4* p = (const float4*)(emb + c * D);
        float s = 0.0f;
#pragma unroll
        for (int i = 0; i < 16; i++) {
            float4 v = p[i];
            s += v.x * v.x + v.y * v.y + v.z * v.z + v.w * v.w;
        }
        g_e2[c] = s;
    }
}

// ---------------- K2: fused distance GEMM + argmin + gather + scatter ----------------
// Block: 256 threads = 16 (token groups) x 16 (code groups).
// Thread tile: 8 tokens x 4 codes, f32x2 packed accumulation over k.
__global__ void __launch_bounds__(256, 1)
k_assign(const float* __restrict__ x, const float* __restrict__ emb,
         float* __restrict__ out_q, float* __restrict__ out_ind)
{
    extern __shared__ float smem[];
    float* xs   = smem;                       // [128][64]   32768 B
    float* es   = smem + TPB_TOK * D;         // 2 x [64][68] 34816 B (double buffer)
    int*   sidx = (int*)(es + 2 * CT * ES_STRIDE); // [128]  512 B

    const int tid = threadIdx.x;
    const int tx  = tid & 15;   // code group
    const int ty  = tid >> 4;   // token group
    const int tokBase = blockIdx.x * TPB_TOK;

    // Load x tile (coalesced float4): 2048 float4 / 256 threads
    {
        const float4* gx = (const float4*)(x + (size_t)tokBase * D);
        float4* sx = (float4*)xs;
#pragma unroll
        for (int i = 0; i < 8; i++) sx[tid + i * 256] = gx[tid + i * 256];
    }

    // Prefetch code tile 0
    {
#pragma unroll
        for (int i = 0; i < 4; i++) {
            int idx = tid + i * 256;
            int c = idx >> 4, q = idx & 15;
            cp_async16(&es[c * ES_STRIDE + q * 4], emb + (size_t)c * D + q * 4);
        }
        cp_commit();
    }

    float bestVal[8];
    int   bestIdx[8];
#pragma unroll
    for (int t = 0; t < 8; t++) { bestVal[t] = 3.4e38f; bestIdx[t] = 0; }

    for (int tile = 0; tile < NTILES; tile++) {
        float* esCur = es + (tile & 1) * CT * ES_STRIDE;

        // Prefetch next tile into other buffer
        if (tile + 1 < NTILES) {
            float* esNext = es + ((tile + 1) & 1) * CT * ES_STRIDE;
#pragma unroll
            for (int i = 0; i < 4; i++) {
                int idx = tid + i * 256;
                int c = idx >> 4, q = idx & 15;
                cp_async16(&esNext[c * ES_STRIDE + q * 4],
                           emb + ((size_t)(tile + 1) * CT + c) * D + q * 4);
            }
            cp_commit();
            asm volatile("cp.async.wait_group 1;\n" ::: "memory");  // current tile ready
        } else {
            asm volatile("cp.async.wait_group 0;\n" ::: "memory");
        }
        __syncthreads();

        // Packed f32x2 accumulators: 8 tokens x 4 codes
        unsigned long long acc[8][4];
#pragma unroll
        for (int t = 0; t < 8; t++)
#pragma unroll
            for (int u = 0; u < 4; u++) acc[t][u] = 0ull;

#pragma unroll
        for (int k4 = 0; k4 < 16; k4++) {
            ulonglong2 xf[8], ef[4];
#pragma unroll
            for (int t = 0; t < 8; t++)
                xf[t] = *(const ulonglong2*)&xs[(ty * 8 + t) * D + k4 * 4];
#pragma unroll
            for (int u = 0; u < 4; u++)
                ef[u] = *(const ulonglong2*)&esCur[(tx * 4 + u) * ES_STRIDE + k4 * 4];
#pragma unroll
            for (int t = 0; t < 8; t++)
#pragma unroll
                for (int u = 0; u < 4; u++) {
                    fma2(acc[t][u], xf[t].x, ef[u].x);
                    fma2(acc[t][u], xf[t].y, ef[u].y);
                }
        }

        // Score and fold into running argmin (codes visited in increasing index:
        // strict < keeps the earliest index on exact ties, matching argmax-first)
        float4 e2v = *(const float4*)&g_e2[tile * CT + tx * 4];
        float e2a[4] = {e2v.x, e2v.y, e2v.z, e2v.w};
#pragma unroll
        for (int t = 0; t < 8; t++) {
#pragma unroll
            for (int u = 0; u < 4; u++) {
                float lo = __uint_as_float((unsigned)(acc[t][u] & 0xffffffffull));
                float hi = __uint_as_float((unsigned)(acc[t][u] >> 32));
                float s  = e2a[u] - 2.0f * (lo + hi);
                int   ci = tile * CT + tx * 4 + u;
                if (s < bestVal[t]) { bestVal[t] = s; bestIdx[t] = ci; }
            }
        }
        __syncthreads();  // protect esCur before next prefetch overwrites it
    }

    // Cross-thread argmin over the 16 code-group lanes (within each half-warp)
#pragma unroll
    for (int t = 0; t < 8; t++) {
        float v = bestVal[t];
        int   id = bestIdx[t];
#pragma unroll
        for (int off = 8; off >= 1; off >>= 1) {
            float ov = __shfl_xor_sync(0xffffffffu, v, off);
            int   oi = __shfl_xor_sync(0xffffffffu, id, off);
            if (ov < v || (ov == v && oi < id)) { v = ov; id = oi; }
        }
        if (tx == 0) sidx[ty * 8 + t] = id;
    }
    __syncthreads();

    // Epilogue: gather quantize, write indices, scatter counts / embed_sum
    {
        int tk   = tid >> 1;     // token within tile (2 threads per token)
        int half = tid & 1;      // each thread covers 32 dims
        int idx  = sidx[tk];
        int gtok = tokBase + tk;
        if (half == 0) {
            atomicAdd(&g_counts[idx], 1.0f);
            out_ind[gtok] = (float)idx;
        }
        const float4* ev = (const float4*)(emb + (size_t)idx * D + half * 32);
        const float4* xv = (const float4*)(xs + tk * D + half * 32);
        float4* qo = (float4*)(out_q + (size_t)gtok * D + half * 32);
        float* esum = g_embed_sum + (size_t)idx * D + half * 32;
#pragma unroll
        for (int i = 0; i < 8; i++) {
            qo[i] = ev[i];
            float4 v = xv[i];
            atomicAdd(esum + i * 4 + 0, v.x);
            atomicAdd(esum + i * 4 + 1, v.y);
            atomicAdd(esum + i * 4 + 2, v.z);
            atomicAdd(esum + i * 4 + 3, v.w);
        }
    }
}

// ---------------- K3: cluster-size EMA + laplace smoothing (single block) ----------------
__global__ void k_cluster(const float* __restrict__ cs, float* __restrict__ out_cs) {
    __shared__ float red[32];
    __shared__ float s_tot;
    int tid = threadIdx.x;  // 1024
    float ncs[2];
    float local = 0.0f;
#pragma unroll
    for (int i = 0; i < 2; i++) {
        int c = tid + i * 1024;
        ncs[i] = cs[c] * DECAY + g_counts[c] * (1.0f - DECAY);
        out_cs[c] = ncs[i];
        local += ncs[i];
    }
#pragma unroll
    for (int o = 16; o; o >>= 1) local += __shfl_xor_sync(0xffffffffu, local, o);
    if ((tid & 31) == 0) red[tid >> 5] = local;
    __syncthreads();
    if (tid < 32) {
        float v = red[tid];
#pragma unroll
        for (int o = 16; o; o >>= 1) v += __shfl_xor_sync(0xffffffffu, v, o);
        if (tid == 0) s_tot = v;
    }
    __syncthreads();
    float tot = s_tot;
#pragma unroll
    for (int i = 0; i < 2; i++) {
        int c = tid + i * 1024;
        g_smooth[c] = (ncs[i] + EPSV) / (tot + (float)C * EPSV) * tot;
    }
}

// ---------------- K4: embed_avg EMA + renormalized embeddings ----------------
__global__ void k_embed(const float* __restrict__ ea,
                        float* __restrict__ out_emb, float* __restrict__ out_ea) {
    int i = blockIdx.x * 256 + threadIdx.x;  // over 32768 float4
    int c = i >> 4;
    float4 e = ((const float4*)ea)[i];
    float4 s = ((const float4*)g_embed_sum)[i];
    float4 na;
    na.x = e.x * DECAY + s.x * (1.0f - DECAY);
    na.y = e.y * DECAY + s.y * (1.0f - DECAY);
    na.z = e.z * DECAY + s.z * (1.0f - DECAY);
    na.w = e.w * DECAY + s.w * (1.0f - DECAY);
    ((float4*)out_ea)[i] = na;
    float sm = g_smooth[c];
    float4 ne;
    ne.x = na.x / sm; ne.y = na.y / sm; ne.z = na.z / sm; ne.w = na.w / sm;
    ((float4*)out_emb)[i] = ne;
}

// ---------------- launch ----------------
extern "C" void kernel_launch(void* const* d_in, const int* in_sizes, int n_in,
                              void* d_out, int out_size) {
    const float* x   = (const float*)d_in[0];
    const float* emb = (const float*)d_in[1];
    const float* cs  = (const float*)d_in[2];
    const float* ea  = (const float*)d_in[3];
    float* out = (float*)d_out;

    float* out_q   = out;
    float* out_ind = out + OFF_IND;
    float* out_emb = out + OFF_EMB;
    float* out_cs  = out + OFF_CS;
    float* out_ea  = out + OFF_EA;

    const int smem_bytes = (TPB_TOK * D + 2 * CT * ES_STRIDE) * 4 + TPB_TOK * 4;  // 68096
    cudaFuncSetAttribute(k_assign, cudaFuncAttributeMaxDynamicSharedMemorySize, smem_bytes);

    k_zero<<<(C * D + 255) / 256, 256>>>();
    k_e2<<<(C + 255) / 256, 256>>>(emb);
    k_assign<<<NT / TPB_TOK, 256, smem_bytes>>>(x, emb, out_q, out_ind);
    k_cluster<<<1, 1024>>>(cs, out_cs);
    k_embed<<<(C * D / 4 + 255) / 256, 256>>>(ea, out_emb, out_ea);
}

// round 5
// speedup vs baseline: 1.8313x; 1.8313x over previous
#include <cuda_runtime.h>
#include <cstdint>

// Problem constants
#define NT       65536     // tokens = 16*4096
#define D        64        // feature dim
#define C        2048      // codes
#define TPB_TOK  64        // tokens per block tile
#define CT       128       // codes per smem tile
#define NTILES   (C / CT)  // 16

// Output layout (concatenated fp32, reference return order):
// quantize (4194304) | embed_ind (65536) | new_embeddings (131072) |
// new_cluster_size (2048) | new_embed_avg (131072)
#define OFF_IND  4194304
#define OFF_EMB  4259840
#define OFF_CS   4390912
#define OFF_EA   4392960

#define DECAY    0.8f
#define EPSV     1e-5f

// Scratch (no cudaMalloc allowed)
__device__ float g_embed_sum[C * D];
__device__ float g_counts[C];
__device__ float g_e2[C];
__device__ float g_smooth[C];

// ---------------- helpers ----------------
__device__ __forceinline__ void cp_async16(void* smem_dst, const void* gmem_src) {
    uint32_t s = (uint32_t)__cvta_generic_to_shared(smem_dst);
    asm volatile("cp.async.cg.shared.global [%0], [%1], 16;\n" :: "r"(s), "l"(gmem_src));
}
__device__ __forceinline__ void cp_commit() {
    asm volatile("cp.async.commit_group;\n" ::: "memory");
}
__device__ __forceinline__ void fma2(unsigned long long& acc, unsigned long long a, unsigned long long b) {
    asm("fma.rn.f32x2 %0, %1, %2, %0;" : "+l"(acc) : "l"(a), "l"(b));
}

// ---------------- K0: zero scatter scratch ----------------
__global__ void k_zero() {
    int i = blockIdx.x * 256 + threadIdx.x;
    if (i < C * D) g_embed_sum[i] = 0.0f;
    if (i < C)     g_counts[i]    = 0.0f;
}

// ---------------- K1: per-code squared norms ----------------
__global__ void k_e2(const float* __restrict__ emb) {
    int c = blockIdx.x * 256 + threadIdx.x;
    if (c < C) {
        const float4* p = (const float4*)(emb + c * D);
        float s = 0.0f;
#pragma unroll
        for (int i = 0; i < 16; i++) {
            float4 v = p[i];
            s += v.x * v.x + v.y * v.y + v.z * v.z + v.w * v.w;
        }
        g_e2[c] = s;
    }
}

// ---------------- K2: fused distance GEMM + argmin + gather + scatter ----------------
// Block: 128 threads = 16 (tx: code groups) x 8 (ty: token groups).
// Thread tile: 8 tokens x 8 codes (interleaved: code = u*16 + tx within tile).
// Code tile in smem is XOR-swizzled: 16B chunk q of row c lives at chunk q ^ (c & 15),
// making every ef LDS.128 conflict-free (2 wavefronts, the bandwidth minimum).
__global__ void __launch_bounds__(128, 2)
k_assign(const float* __restrict__ x, const float* __restrict__ emb,
         float* __restrict__ out_q, float* __restrict__ out_ind)
{
    extern __shared__ float smem[];
    float* xs   = smem;                        // [64][64]          16384 B
    float* es   = smem + TPB_TOK * D;          // 2 x [128][64]     65536 B (double buffer, swizzled)
    int*   sidx = (int*)(es + 2 * CT * D);     // [64]              256 B

    const int tid = threadIdx.x;
    const int tx  = tid & 15;   // code lane
    const int ty  = tid >> 4;   // token group (0..7)
    const int tokBase = blockIdx.x * TPB_TOK;

    // Load x tile (coalesced float4): 1024 float4 / 128 threads
    {
        const float4* gx = (const float4*)(x + (size_t)tokBase * D);
        float4* sx = (float4*)xs;
#pragma unroll
        for (int i = 0; i < 8; i++) sx[tid + i * 128] = gx[tid + i * 128];
    }

    // Prefetch code tile 0 (swizzled): 2048 chunks / 128 threads = 16 each
    {
#pragma unroll
        for (int i = 0; i < 16; i++) {
            int idx = tid + i * 128;
            int c = idx >> 4, q = idx & 15;
            cp_async16(&es[c * D + ((q ^ (c & 15)) << 2)], emb + (size_t)c * D + q * 4);
        }
        cp_commit();
    }

    float bestVal[8];
    int   bestIdx[8];
#pragma unroll
    for (int t = 0; t < 8; t++) { bestVal[t] = 3.4e38f; bestIdx[t] = 0; }

    for (int tile = 0; tile < NTILES; tile++) {
        const float* esCur = es + (tile & 1) * CT * D;

        // Prefetch next tile into other buffer
        if (tile + 1 < NTILES) {
            float* esNext = es + ((tile + 1) & 1) * CT * D;
#pragma unroll
            for (int i = 0; i < 16; i++) {
                int idx = tid + i * 128;
                int c = idx >> 4, q = idx & 15;
                cp_async16(&esNext[c * D + ((q ^ (c & 15)) << 2)],
                           emb + ((size_t)(tile + 1) * CT + c) * D + q * 4);
            }
            cp_commit();
            asm volatile("cp.async.wait_group 1;\n" ::: "memory");  // current tile ready
        } else {
            asm volatile("cp.async.wait_group 0;\n" ::: "memory");
        }
        __syncthreads();

        // Packed f32x2 accumulators: 8 tokens x 8 codes (even/odd k partial sums)
        unsigned long long acc[8][8];
#pragma unroll
        for (int t = 0; t < 8; t++)
#pragma unroll
            for (int u = 0; u < 8; u++) acc[t][u] = 0ull;

        const float* xbase = xs + ty * 8 * D;
        const float* ebase = esCur + tx * D;   // row (u*16+tx) = +u*16*D from here

#pragma unroll 8
        for (int k4 = 0; k4 < 16; k4++) {
            const int swoff = ((k4 ^ tx) << 2);  // swizzled chunk offset (floats)
            ulonglong2 ef[8];
#pragma unroll
            for (int u = 0; u < 8; u++)
                ef[u] = *(const ulonglong2*)(ebase + u * 16 * D + swoff);
#pragma unroll
            for (int t = 0; t < 8; t++) {
                ulonglong2 xf = *(const ulonglong2*)(xbase + t * D + k4 * 4);
#pragma unroll
                for (int u = 0; u < 8; u++) {
                    fma2(acc[t][u], xf.x, ef[u].x);
                    fma2(acc[t][u], xf.y, ef[u].y);
                }
            }
        }

        // Score and fold into running argmin. Per-thread code indices increase
        // monotonically (tile asc, u asc), so strict < keeps the earliest index
        // on exact ties, matching argmax-first semantics.
#pragma unroll
        for (int u = 0; u < 8; u++) {
            int   ci = tile * CT + u * 16 + tx;
            float e2 = __ldg(&g_e2[ci]);
#pragma unroll
            for (int t = 0; t < 8; t++) {
                float lo = __uint_as_float((unsigned)(acc[t][u] & 0xffffffffull));
                float hi = __uint_as_float((unsigned)(acc[t][u] >> 32));
                float s  = e2 - 2.0f * (lo + hi);
                if (s < bestVal[t]) { bestVal[t] = s; bestIdx[t] = ci; }
            }
        }
        __syncthreads();  // protect esCur before next prefetch overwrites it
    }

    // Cross-thread argmin over the 16 code lanes (xor stays within 16-lane halves)
#pragma unroll
    for (int t = 0; t < 8; t++) {
        float v = bestVal[t];
        int   id = bestIdx[t];
#pragma unroll
        for (int off = 8; off >= 1; off >>= 1) {
            float ov = __shfl_xor_sync(0xffffffffu, v, off);
            int   oi = __shfl_xor_sync(0xffffffffu, id, off);
            if (ov < v || (ov == v && oi < id)) { v = ov; id = oi; }
        }
        if (tx == 0) sidx[ty * 8 + t] = id;
    }
    __syncthreads();

    // Epilogue: gather quantize, write indices, scatter counts / embed_sum
    {
        int tk   = tid >> 1;     // token within tile (2 threads per token)
        int half = tid & 1;      // each thread covers 32 dims
        int idx  = sidx[tk];
        int gtok = tokBase + tk;
        if (half == 0) {
            atomicAdd(&g_counts[idx], 1.0f);
            out_ind[gtok] = (float)idx;
        }
        const float4* ev = (const float4*)(emb + (size_t)idx * D + half * 32);
        const float4* xv = (const float4*)(xs + tk * D + half * 32);
        float4* qo = (float4*)(out_q + (size_t)gtok * D + half * 32);
        float* esum = g_embed_sum + (size_t)idx * D + half * 32;
#pragma unroll
        for (int i = 0; i < 8; i++) {
            qo[i] = ev[i];
            float4 v = xv[i];
            atomicAdd(esum + i * 4 + 0, v.x);
            atomicAdd(esum + i * 4 + 1, v.y);
            atomicAdd(esum + i * 4 + 2, v.z);
            atomicAdd(esum + i * 4 + 3, v.w);
        }
    }
}

// ---------------- K3: cluster-size EMA + laplace smoothing (single block) ----------------
__global__ void k_cluster(const float* __restrict__ cs, float* __restrict__ out_cs) {
    __shared__ float red[32];
    __shared__ float s_tot;
    int tid = threadIdx.x;  // 1024
    float ncs[2];
    float local = 0.0f;
#pragma unroll
    for (int i = 0; i < 2; i++) {
        int c = tid + i * 1024;
        ncs[i] = cs[c] * DECAY + g_counts[c] * (1.0f - DECAY);
        out_cs[c] = ncs[i];
        local += ncs[i];
    }
#pragma unroll
    for (int o = 16; o; o >>= 1) local += __shfl_xor_sync(0xffffffffu, local, o);
    if ((tid & 31) == 0) red[tid >> 5] = local;
    __syncthreads();
    if (tid < 32) {
        float v = red[tid];
#pragma unroll
        for (int o = 16; o; o >>= 1) v += __shfl_xor_sync(0xffffffffu, v, o);
        if (tid == 0) s_tot = v;
    }
    __syncthreads();
    float tot = s_tot;
#pragma unroll
    for (int i = 0; i < 2; i++) {
        int c = tid + i * 1024;
        g_smooth[c] = (ncs[i] + EPSV) / (tot + (float)C * EPSV) * tot;
    }
}

// ---------------- K4: embed_avg EMA + renormalized embeddings ----------------
__global__ void k_embed(const float* __restrict__ ea,
                        float* __restrict__ out_emb, float* __restrict__ out_ea) {
    int i = blockIdx.x * 256 + threadIdx.x;  // over 32768 float4
    int c = i >> 4;
    float4 e = ((const float4*)ea)[i];
    float4 s = ((const float4*)g_embed_sum)[i];
    float4 na;
    na.x = e.x * DECAY + s.x * (1.0f - DECAY);
    na.y = e.y * DECAY + s.y * (1.0f - DECAY);
    na.z = e.z * DECAY + s.z * (1.0f - DECAY);
    na.w = e.w * DECAY + s.w * (1.0f - DECAY);
    ((float4*)out_ea)[i] = na;
    float sm = g_smooth[c];
    float4 ne;
    ne.x = na.x / sm; ne.y = na.y / sm; ne.z = na.z / sm; ne.w = na.w / sm;
    ((float4*)out_emb)[i] = ne;
}

// ---------------- launch ----------------
extern "C" void kernel_launch(void* const* d_in, const int* in_sizes, int n_in,
                              void* d_out, int out_size) {
    const float* x   = (const float*)d_in[0];
    const float* emb = (const float*)d_in[1];
    const float* cs  = (const float*)d_in[2];
    const float* ea  = (const float*)d_in[3];
    float* out = (float*)d_out;

    float* out_q   = out;
    float* out_ind = out + OFF_IND;
    float* out_emb = out + OFF_EMB;
    float* out_cs  = out + OFF_CS;
    float* out_ea  = out + OFF_EA;

    const int smem_bytes = (TPB_TOK * D + 2 * CT * D) * 4 + TPB_TOK * 4;  // 82176
    cudaFuncSetAttribute(k_assign, cudaFuncAttributeMaxDynamicSharedMemorySize, smem_bytes);

    k_zero<<<(C * D + 255) / 256, 256>>>();
    k_e2<<<(C + 255) / 256, 256>>>(emb);
    k_assign<<<NT / TPB_TOK, 128, smem_bytes>>>(x, emb, out_q, out_ind);
    k_cluster<<<1, 1024>>>(cs, out_cs);
    k_embed<<<(C * D / 4 + 255) / 256, 256>>>(ea, out_emb, out_ea);
}

// round 6
// speedup vs baseline: 1.9665x; 1.0738x over previous
#include <cuda_runtime.h>
#include <cstdint>

// Problem constants
#define NT       65536     // tokens = 16*4096
#define D        64        // feature dim
#define C        2048      // codes
#define TPB_TOK  32        // tokens per block tile
#define CT       128       // codes per smem tile
#define NTILES   (C / CT)  // 16
#define XS_STRIDE 68       // padded x-tile row stride (floats) -> conflict-free xf loads

// Output layout (concatenated fp32, reference return order):
// quantize (4194304) | embed_ind (65536) | new_embeddings (131072) |
// new_cluster_size (2048) | new_embed_avg (131072)
#define OFF_IND  4194304
#define OFF_EMB  4259840
#define OFF_CS   4390912
#define OFF_EA   4392960

#define DECAY    0.8f
#define EPSV     1e-5f

// Scratch (no cudaMalloc allowed)
__device__ float g_embed_sum[C * D];
__device__ float g_counts[C];
__device__ float g_e2[C];
__device__ float g_smooth[C];

// ---------------- helpers ----------------
__device__ __forceinline__ void cp_async16(void* smem_dst, const void* gmem_src) {
    uint32_t s = (uint32_t)__cvta_generic_to_shared(smem_dst);
    asm volatile("cp.async.cg.shared.global [%0], [%1], 16;\n" :: "r"(s), "l"(gmem_src));
}
__device__ __forceinline__ void cp_commit() {
    asm volatile("cp.async.commit_group;\n" ::: "memory");
}
__device__ __forceinline__ void fma2(unsigned long long& acc, unsigned long long a, unsigned long long b) {
    asm("fma.rn.f32x2 %0, %1, %2, %0;" : "+l"(acc) : "l"(a), "l"(b));
}
__device__ __forceinline__ void mul2(unsigned long long& acc, unsigned long long a, unsigned long long b) {
    asm("mul.rn.f32x2 %0, %1, %2;" : "=l"(acc) : "l"(a), "l"(b));
}

// ---------------- K1: zero scatter scratch + per-code squared norms ----------------
__global__ void k_init(const float* __restrict__ emb) {
    int i = blockIdx.x * 256 + threadIdx.x;
    if (i < C * D) g_embed_sum[i] = 0.0f;
    if (i < C) {
        g_counts[i] = 0.0f;
        const float4* p = (const float4*)(emb + i * D);
        float s = 0.0f;
#pragma unroll
        for (int j = 0; j < 16; j++) {
            float4 v = p[j];
            s += v.x * v.x + v.y * v.y + v.z * v.z + v.w * v.w;
        }
        g_e2[i] = s;
    }
}

// ---------------- K2: fused distance GEMM + argmin + gather + scatter ----------------
// Block: 128 threads = 16 (tx: code lanes) x 8 (ty: token groups of 4).
// Thread tile: 4 tokens x 8 codes (code = u*16 + tx within tile).
// Code tile XOR-swizzled (chunk q of row c at q ^ (c & 15)) -> ef LDS.128 conflict-free.
// x tile padded to stride 68 -> xf LDS.128 conflict-free.
// k4==0 peeled with mul.rn.f32x2 -> no accumulator zero-init.
__global__ void __launch_bounds__(128, 2)
k_assign(const float* __restrict__ x, const float* __restrict__ emb,
         float* __restrict__ out_q, float* __restrict__ out_ind)
{
    extern __shared__ float smem[];
    float* xs   = smem;                          // [32][68]        8704 B (padded)
    float* es   = smem + TPB_TOK * XS_STRIDE;    // 2 x [128][64]   65536 B (double buffer, swizzled)
    int*   sidx = (int*)(es + 2 * CT * D);       // [32]            128 B

    const int tid = threadIdx.x;
    const int tx  = tid & 15;   // code lane
    const int ty  = tid >> 4;   // token group (0..7), 4 tokens each
    const int tokBase = blockIdx.x * TPB_TOK;

    // Load x tile into padded layout: 512 float4 / 128 threads = 4 each
    {
        const float4* gx = (const float4*)(x + (size_t)tokBase * D);
#pragma unroll
        for (int i = 0; i < 4; i++) {
            int idx = tid + i * 128;           // 0..511
            int r = idx >> 4, q = idx & 15;
            *(float4*)&xs[r * XS_STRIDE + q * 4] = gx[idx];
        }
    }

    // Prefetch code tile 0 (swizzled): 2048 chunks / 128 threads = 16 each
    {
#pragma unroll
        for (int i = 0; i < 16; i++) {
            int idx = tid + i * 128;
            int c = idx >> 4, q = idx & 15;
            cp_async16(&es[c * D + ((q ^ (c & 15)) << 2)], emb + (size_t)c * D + q * 4);
        }
        cp_commit();
    }

    float bestVal[4];
    int   bestIdx[4];
#pragma unroll
    for (int t = 0; t < 4; t++) { bestVal[t] = 3.4e38f; bestIdx[t] = 0; }

    for (int tile = 0; tile < NTILES; tile++) {
        const float* esCur = es + (tile & 1) * CT * D;

        // Prefetch next tile into other buffer
        if (tile + 1 < NTILES) {
            float* esNext = es + ((tile + 1) & 1) * CT * D;
#pragma unroll
            for (int i = 0; i < 16; i++) {
                int idx = tid + i * 128;
                int c = idx >> 4, q = idx & 15;
                cp_async16(&esNext[c * D + ((q ^ (c & 15)) << 2)],
                           emb + ((size_t)(tile + 1) * CT + c) * D + q * 4);
            }
            cp_commit();
            asm volatile("cp.async.wait_group 1;\n" ::: "memory");  // current tile ready
        } else {
            asm volatile("cp.async.wait_group 0;\n" ::: "memory");
        }
        __syncthreads();

        // Packed f32x2 accumulators: 4 tokens x 8 codes (even/odd k partial sums)
        unsigned long long acc[4][8];

        const float* xbase = xs + ty * 4 * XS_STRIDE;
        const float* ebase = esCur + tx * D;   // row (u*16+tx) = +u*16*D from here

        // ---- k4 = 0 peeled: mul writes acc (no zero-init) ----
        {
            const int swoff = (tx << 2);       // (0 ^ tx) chunk
            ulonglong2 ef[8];
#pragma unroll
            for (int u = 0; u < 8; u++)
                ef[u] = *(const ulonglong2*)(ebase + u * 16 * D + swoff);
#pragma unroll
            for (int t = 0; t < 4; t++) {
                ulonglong2 xf = *(const ulonglong2*)(xbase + t * XS_STRIDE);
#pragma unroll
                for (int u = 0; u < 8; u++) {
                    mul2(acc[t][u], xf.x, ef[u].x);
                    fma2(acc[t][u], xf.y, ef[u].y);
                }
            }
        }

#pragma unroll
        for (int k4 = 1; k4 < 16; k4++) {
            const int swoff = ((k4 ^ tx) << 2);  // swizzled chunk offset (floats)
            ulonglong2 ef[8];
#pragma unroll
            for (int u = 0; u < 8; u++)
                ef[u] = *(const ulonglong2*)(ebase + u * 16 * D + swoff);
#pragma unroll
            for (int t = 0; t < 4; t++) {
                ulonglong2 xf = *(const ulonglong2*)(xbase + t * XS_STRIDE + k4 * 4);
#pragma unroll
                for (int u = 0; u < 8; u++) {
                    fma2(acc[t][u], xf.x, ef[u].x);
                    fma2(acc[t][u], xf.y, ef[u].y);
                }
            }
        }

        // Score and fold into running argmin. Per-thread code indices increase
        // monotonically (tile asc, u asc); strict < keeps the earliest index
        // on exact ties, matching argmax-first semantics.
#pragma unroll
        for (int u = 0; u < 8; u++) {
            int   ci = tile * CT + u * 16 + tx;
            float e2 = __ldg(&g_e2[ci]);
#pragma unroll
            for (int t = 0; t < 4; t++) {
                float lo = __uint_as_float((unsigned)(acc[t][u] & 0xffffffffull));
                float hi = __uint_as_float((unsigned)(acc[t][u] >> 32));
                float s  = fmaf(-2.0f, lo + hi, e2);
                if (s < bestVal[t]) { bestVal[t] = s; bestIdx[t] = ci; }
            }
        }
        __syncthreads();  // protect esCur before next prefetch overwrites it
    }

    // Cross-thread argmin over the 16 code lanes (xor stays within 16-lane halves)
#pragma unroll
    for (int t = 0; t < 4; t++) {
        float v = bestVal[t];
        int   id = bestIdx[t];
#pragma unroll
        for (int off = 8; off >= 1; off >>= 1) {
            float ov = __shfl_xor_sync(0xffffffffu, v, off);
            int   oi = __shfl_xor_sync(0xffffffffu, id, off);
            if (ov < v || (ov == v && oi < id)) { v = ov; id = oi; }
        }
        if (tx == 0) sidx[ty * 4 + t] = id;
    }
    __syncthreads();

    // Epilogue: gather quantize, write indices, scatter counts / embed_sum.
    // 4 threads per token, each covers 16 dims.
    {
        int tk   = tid >> 2;     // token within tile (0..31)
        int part = tid & 3;      // 16-dim slice
        int idx  = sidx[tk];
        int gtok = tokBase + tk;
        if (part == 0) {
            atomicAdd(&g_counts[idx], 1.0f);
            out_ind[gtok] = (float)idx;
        }
        const float4* ev = (const float4*)(emb + (size_t)idx * D + part * 16);
        const float4* xv = (const float4*)(xs + tk * XS_STRIDE + part * 16);
        float4* qo = (float4*)(out_q + (size_t)gtok * D + part * 16);
        float* esum = g_embed_sum + (size_t)idx * D + part * 16;
#pragma unroll
        for (int i = 0; i < 4; i++) {
            qo[i] = ev[i];
            float4 v = xv[i];
            atomicAdd(esum + i * 4 + 0, v.x);
            atomicAdd(esum + i * 4 + 1, v.y);
            atomicAdd(esum + i * 4 + 2, v.z);
            atomicAdd(esum + i * 4 + 3, v.w);
        }
    }
}

// ---------------- K3: cluster-size EMA + laplace smoothing (single block) ----------------
__global__ void k_cluster(const float* __restrict__ cs, float* __restrict__ out_cs) {
    __shared__ float red[32];
    __shared__ float s_tot;
    int tid = threadIdx.x;  // 1024
    float ncs[2];
    float local = 0.0f;
#pragma unroll
    for (int i = 0; i < 2; i++) {
        int c = tid + i * 1024;
        ncs[i] = cs[c] * DECAY + g_counts[c] * (1.0f - DECAY);
        out_cs[c] = ncs[i];
        local += ncs[i];
    }
#pragma unroll
    for (int o = 16; o; o >>= 1) local += __shfl_xor_sync(0xffffffffu, local, o);
    if ((tid & 31) == 0) red[tid >> 5] = local;
    __syncthreads();
    if (tid < 32) {
        float v = red[tid];
#pragma unroll
        for (int o = 16; o; o >>= 1) v += __shfl_xor_sync(0xffffffffu, v, o);
        if (tid == 0) s_tot = v;
    }
    __syncthreads();
    float tot = s_tot;
#pragma unroll
    for (int i = 0; i < 2; i++) {
        int c = tid + i * 1024;
        g_smooth[c] = (ncs[i] + EPSV) / (tot + (float)C * EPSV) * tot;
    }
}

// ---------------- K4: embed_avg EMA + renormalized embeddings ----------------
__global__ void k_embed(const float* __restrict__ ea,
                        float* __restrict__ out_emb, float* __restrict__ out_ea) {
    int i = blockIdx.x * 256 + threadIdx.x;  // over 32768 float4
    int c = i >> 4;
    float4 e = ((const float4*)ea)[i];
    float4 s = ((const float4*)g_embed_sum)[i];
    float4 na;
    na.x = e.x * DECAY + s.x * (1.0f - DECAY);
    na.y = e.y * DECAY + s.y * (1.0f - DECAY);
    na.z = e.z * DECAY + s.z * (1.0f - DECAY);
    na.w = e.w * DECAY + s.w * (1.0f - DECAY);
    ((float4*)out_ea)[i] = na;
    float sm = g_smooth[c];
    float4 ne;
    ne.x = na.x / sm; ne.y = na.y / sm; ne.z = na.z / sm; ne.w = na.w / sm;
    ((float4*)out_emb)[i] = ne;
}

// ---------------- launch ----------------
extern "C" void kernel_launch(void* const* d_in, const int* in_sizes, int n_in,
                              void* d_out, int out_size) {
    const float* x   = (const float*)d_in[0];
    const float* emb = (const float*)d_in[1];
    const float* cs  = (const float*)d_in[2];
    const float* ea  = (const float*)d_in[3];
    float* out = (float*)d_out;

    float* out_q   = out;
    float* out_ind = out + OFF_IND;
    float* out_emb = out + OFF_EMB;
    float* out_cs  = out + OFF_CS;
    float* out_ea  = out + OFF_EA;

    const int smem_bytes = (TPB_TOK * XS_STRIDE + 2 * CT * D) * 4 + TPB_TOK * 4;  // 74368
    cudaFuncSetAttribute(k_assign, cudaFuncAttributeMaxDynamicSharedMemorySize, smem_bytes);

    k_init<<<(C * D + 255) / 256, 256>>>(emb);
    k_assign<<<NT / TPB_TOK, 128, smem_bytes>>>(x, emb, out_q, out_ind);
    k_cluster<<<1, 1024>>>(cs, out_cs);
    k_embed<<<(C * D / 4 + 255) / 256, 256>>>(ea, out_emb, out_ea);
}

// round 9
// speedup vs baseline: 2.1587x; 1.0977x over previous
#include <cuda_runtime.h>
#include <cuda_fp16.h>
#include <cstdint>

// Problem constants
#define NT       65536     // tokens
#define D        64        // feature dim
#define C        2048      // codes
#define M_CTA    128       // tokens per CTA (8 warps x 16)
#define NTILE    64        // codes per N-tile
#define NTILES   (C / NTILE)  // 32
#define MARGIN   1e-3f     // ambiguity margin (>= 10x worst-case 3-term fp16 error)

// Output layout (concatenated fp32, reference return order)
#define OFF_IND  4194304
#define OFF_EMB  4259840
#define OFF_CS   4390912
#define OFF_EA   4392960

#define DECAY    0.8f
#define EPSV     1e-5f

// SMEM byte offsets (k_assign)
#define XHI_OFF   0        // 128 rows x 128B (half)  = 16384
#define XLO_OFF   16384
#define B_OFF     32768    // 2 bufs x (hi 8192 | lo 8192) = 32768
#define E2_OFF    65536    // 2048 floats = 8192
#define SIDX_OFF  73728    // 128 ints = 512
#define SMEM_ASGN 74240

// Scratch (no cudaMalloc allowed)
__device__ float  g_embed_sum[C * D];
__device__ float  g_counts[C];
__device__ float  g_e2[C];
__device__ float  g_smooth[C];
__device__ __half g_ehi[C * D];   // fp16(-2*emb)
__device__ __half g_elo[C * D];   // fp16 residual
__device__ int    g_list[NT];     // ambiguous token ids
__device__ int    g_ncand;

// ---------------- PTX helpers (generic sm_80-class only) ----------------
__device__ __forceinline__ uint32_t smem_u32(const void* p) {
    uint32_t a;
    asm("{ .reg .u64 t; cvta.to.shared.u64 t, %1; cvt.u32.u64 %0, t; }" : "=r"(a) : "l"(p));
    return a;
}
__device__ __forceinline__ void cp_async16(uint32_t smem_dst, const void* gmem_src) {
    asm volatile("cp.async.cg.shared.global [%0], [%1], 16;\n" :: "r"(smem_dst), "l"(gmem_src));
}
__device__ __forceinline__ void cp_commit() {
    asm volatile("cp.async.commit_group;\n" ::: "memory");
}
__device__ __forceinline__ void ldsm4(uint32_t* r, uint32_t addr) {
    asm volatile("ldmatrix.sync.aligned.m8n8.x4.shared.b16 {%0,%1,%2,%3}, [%4];"
                 : "=r"(r[0]), "=r"(r[1]), "=r"(r[2]), "=r"(r[3]) : "r"(addr));
}
__device__ __forceinline__ void mma16816(float* d, const uint32_t* a, const uint32_t* b, const float* c) {
    asm volatile(
        "mma.sync.aligned.m16n8k16.row.col.f32.f16.f16.f32 "
        "{%0,%1,%2,%3}, {%4,%5,%6,%7}, {%8,%9}, {%10,%11,%12,%13};"
        : "=f"(d[0]), "=f"(d[1]), "=f"(d[2]), "=f"(d[3])
        : "r"(a[0]), "r"(a[1]), "r"(a[2]), "r"(a[3]),
          "r"(b[0]), "r"(b[1]),
          "f"(c[0]), "f"(c[1]), "f"(c[2]), "f"(c[3]));
}

// ---------------- K_prep: e2, split -2e into fp16 hi/lo, zero scratch ----------------
__global__ void k_prep(const float* __restrict__ emb) {
    int i = blockIdx.x * 256 + threadIdx.x;
    if (i == 0) g_ncand = 0;
    if (i < C * D) g_embed_sum[i] = 0.0f;
    if (i < C) {
        g_counts[i] = 0.0f;
        float s = 0.0f;
#pragma unroll 8
        for (int k = 0; k < D; k++) {
            float e = emb[i * D + k];
            s += e * e;
            float b = -2.0f * e;
            __half h = __float2half_rn(b);
            g_ehi[i * D + k] = h;
            g_elo[i * D + k] = __float2half_rn(b - __half2float(h));
        }
        g_e2[i] = s;
    }
}

// ---------------- K_assign: mma.sync fp16-split GEMM + argmin + ambiguity filter ----------------
// 256 threads = 8 warps x 16 tokens. A (x) hi/lo fragments live in registers for the
// whole kernel. Per N-tile of 64 codes: per warp 96 MMAs (3-term split, fp32 accum).
// Tracks best AND second-best; tokens with (second-best) < MARGIN are deferred to k_rescan.
__global__ void __launch_bounds__(256, 2)
k_assign(const float* __restrict__ x, const float* __restrict__ emb,
         float* __restrict__ out_q, float* __restrict__ out_ind)
{
    extern __shared__ char smem[];
    const uint32_t sb = smem_u32(smem);
    const int tid = threadIdx.x;
    const int wid = tid >> 5;
    const int l   = tid & 31;
    const int tokBase = blockIdx.x * M_CTA;

    // B prefetch: tile nt into buf; 1024 x 16B chunks / 256 threads = 4 each
    auto load_b = [&](int nt, int buf) {
        uint32_t base = sb + B_OFF + (uint32_t)buf * 16384u;
#pragma unroll
        for (int i = 0; i < 4; i++) {
            int idx = tid + i * 256;           // 0..1023
            int m = idx >> 9;                  // 0 = hi, 1 = lo
            int rem = idx & 511;
            int row = rem >> 3, c = rem & 7;   // row 0..63, 16B chunk 0..7
            const __half* g = (m ? g_elo : g_ehi) + (size_t)(nt * NTILE + row) * D + c * 8;
            cp_async16(base + m * 8192u + row * 128u + (uint32_t)((c ^ (row & 7)) << 4), g);
        }
    };

    // Prologue: e2 + B0 (group0), B1 (group1)
#pragma unroll
    for (int i = 0; i < 2; i++) {
        int idx = tid + i * 256;               // 0..511 chunks of e2
        cp_async16(sb + E2_OFF + idx * 16, g_e2 + idx * 4);
    }
    load_b(0, 0);
    cp_commit();
    load_b(1, 1);
    cp_commit();

    // x tile: load 128x64 fp32, split to fp16 hi/lo, store swizzled (rows 128B)
    {
        const float4* gx = (const float4*)(x + (size_t)tokBase * D);
#pragma unroll
        for (int i = 0; i < 8; i++) {
            int idx = tid + i * 256;           // 0..2047 = 128 rows x 16 float4
            int r = idx >> 4, q = idx & 15;
            float4 v = gx[idx];
            __half h0 = __float2half_rn(v.x), h1 = __float2half_rn(v.y);
            __half h2 = __float2half_rn(v.z), h3 = __float2half_rn(v.w);
            uint32_t hi01 = (uint32_t)__half_as_ushort(h0) | ((uint32_t)__half_as_ushort(h1) << 16);
            uint32_t hi23 = (uint32_t)__half_as_ushort(h2) | ((uint32_t)__half_as_ushort(h3) << 16);
            __half l0 = __float2half_rn(v.x - __half2float(h0));
            __half l1 = __float2half_rn(v.y - __half2float(h1));
            __half l2 = __float2half_rn(v.z - __half2float(h2));
            __half l3 = __float2half_rn(v.w - __half2float(h3));
            uint32_t lo01 = (uint32_t)__half_as_ushort(l0) | ((uint32_t)__half_as_ushort(l1) << 16);
            uint32_t lo23 = (uint32_t)__half_as_ushort(l2) | ((uint32_t)__half_as_ushort(l3) << 16);
            int c = q >> 1, s = q & 1;         // 16B chunk, 8B half-sel
            uint32_t off = (uint32_t)(r * 128) + (uint32_t)((c ^ (r & 7)) << 4) + (uint32_t)(s * 8);
            *(uint2*)(smem + XHI_OFF + off) = make_uint2(hi01, hi23);
            *(uint2*)(smem + XLO_OFF + off) = make_uint2(lo01, lo23);
        }
    }
    __syncthreads();

    // A fragments (once): m16k16 per kchunk, hi and lo. ldmatrix lane map:
    // grp = l>>3: i0=(m0-7,klo) i1=(m8-15,klo) i2=(m0-7,khi) i3=(m8-15,khi)
    uint32_t Ahi[4][4], Alo[4][4];
    {
        int lr = l & 7, grp = l >> 3;
        int arow = wid * 16 + lr + (grp & 1) * 8;
#pragma unroll
        for (int kc = 0; kc < 4; kc++) {
            int chunk = 2 * kc + (grp >> 1);
            uint32_t off = (uint32_t)(arow * 128) + (uint32_t)((chunk ^ (arow & 7)) << 4);
            ldsm4(Ahi[kc], sb + XHI_OFF + off);
            ldsm4(Alo[kc], sb + XLO_OFF + off);
        }
    }

    // B ldmatrix lane map: i0=(n0-7,klo) i1=(n0-7,khi) i2=(n8-15,klo) i3=(n8-15,khi)
    const int lr = l & 7, grp = l >> 3;
    const int brow_off = lr + (grp >> 1) * 8;
    const int bsel = grp & 1;

    float bestV[2] = {3.4e38f, 3.4e38f};
    float secV[2]  = {3.4e38f, 3.4e38f};
    int   bestI[2] = {0, 0};
    const float zr[4] = {0.0f, 0.0f, 0.0f, 0.0f};

    for (int nt = 0; nt < NTILES; nt++) {
        const int buf = nt & 1;
        if (nt + 1 < NTILES) asm volatile("cp.async.wait_group 1;\n" ::: "memory");
        else                 asm volatile("cp.async.wait_group 0;\n" ::: "memory");
        __syncthreads();   // B[nt] visible to all warps

        const uint32_t bbase = sb + B_OFF + (uint32_t)buf * 16384u;
        float acc[8][4];

#pragma unroll
        for (int kc = 0; kc < 4; kc++) {
            const int chunkB = 2 * kc + bsel;
#pragma unroll
            for (int p = 0; p < 4; p++) {      // n-chunk pairs
                int row = p * 16 + brow_off;
                uint32_t off = (uint32_t)(row * 128) + (uint32_t)((chunkB ^ (row & 7)) << 4);
                uint32_t bh[4], bl[4];
                ldsm4(bh, bbase + off);            // hi half of B
                if (kc == 0) {
                    mma16816(acc[2 * p],     Ahi[0], bh + 0, zr);
                    mma16816(acc[2 * p + 1], Ahi[0], bh + 2, zr);
                } else {
                    mma16816(acc[2 * p],     Ahi[kc], bh + 0, acc[2 * p]);
                    mma16816(acc[2 * p + 1], Ahi[kc], bh + 2, acc[2 * p + 1]);
                }
                mma16816(acc[2 * p],     Alo[kc], bh + 0, acc[2 * p]);
                mma16816(acc[2 * p + 1], Alo[kc], bh + 2, acc[2 * p + 1]);
                ldsm4(bl, bbase + 8192u + off);    // lo half of B
                mma16816(acc[2 * p],     Ahi[kc], bl + 0, acc[2 * p]);
                mma16816(acc[2 * p + 1], Ahi[kc], bl + 2, acc[2 * p + 1]);
            }
        }

        // Fold into per-thread (best, second). Per-thread code indices strictly increase.
#pragma unroll
        for (int n = 0; n < 8; n++) {
            int cbase = nt * NTILE + n * 8 + 2 * (l & 3);
            float2 e2p = *(const float2*)(smem + E2_OFF + (size_t)cbase * 4);
            float s[4] = { e2p.x + acc[n][0], e2p.y + acc[n][1],
                           e2p.x + acc[n][2], e2p.y + acc[n][3] };
#pragma unroll
            for (int q = 0; q < 2; q++) {      // q: column pair (idx cbase, cbase+1)
#pragma unroll
                for (int h = 0; h < 2; h++) {  // h: token half (rows +0 / +8)
                    float sv = s[h * 2 + q];
                    if (sv < bestV[h]) { secV[h] = bestV[h]; bestV[h] = sv; bestI[h] = cbase + q; }
                    else if (sv < secV[h]) { secV[h] = sv; }
                }
            }
        }

        __syncthreads();   // all warps done reading B[buf]
        if (nt + 2 < NTILES) { load_b(nt + 2, buf); cp_commit(); }
    }

    // Quad reduce (lanes sharing a row: l&~3): merge (best, idx, second) triples.
    int* sidx = (int*)(smem + SIDX_OFF);
#pragma unroll
    for (int h = 0; h < 2; h++) {
        float v = bestV[h], sec = secV[h];
        int   id = bestI[h];
#pragma unroll
        for (int off = 1; off <= 2; off <<= 1) {
            float ov = __shfl_xor_sync(0xffffffffu, v, off);
            float os = __shfl_xor_sync(0xffffffffu, sec, off);
            int   oi = __shfl_xor_sync(0xffffffffu, id, off);
            float loser;
            if (ov < v || (ov == v && oi < id)) { loser = v; v = ov; id = oi; }
            else                                { loser = ov; }
            sec = fminf(fminf(sec, os), loser);
        }
        if ((l & 3) == 0) {
            int tk = wid * 16 + (l >> 2) + h * 8;
            if (sec - v < MARGIN) {
                int p = atomicAdd(&g_ncand, 1);
                g_list[p] = tokBase + tk;
                sidx[tk] = -1;                 // defer to k_rescan
            } else {
                sidx[tk] = id;
            }
        }
    }
    __syncthreads();

    // Epilogue (unambiguous tokens only): gather quantize, indices, scatter counts/embed_sum.
    {
        int tk   = tid >> 1;
        int half = tid & 1;
        int idx  = sidx[tk];
        if (idx >= 0) {
            int gtok = tokBase + tk;
            if (half == 0) {
                atomicAdd(&g_counts[idx], 1.0f);
                out_ind[gtok] = (float)idx;
            }
            const float4* ev = (const float4*)(emb + (size_t)idx * D + half * 32);
            const float4* xv = (const float4*)(x + (size_t)gtok * D + half * 32);
            float4* qo = (float4*)(out_q + (size_t)gtok * D + half * 32);
            float* es = g_embed_sum + (size_t)idx * D + half * 32;
#pragma unroll
            for (int i = 0; i < 8; i++) {
                qo[i] = ev[i];
                float4 v = xv[i];
                atomicAdd(es + i * 4 + 0, v.x);
                atomicAdd(es + i * 4 + 1, v.y);
                atomicAdd(es + i * 4 + 2, v.z);
                atomicAdd(es + i * 4 + 3, v.w);
            }
        }
    }
}

// ---------------- K_rescan: exact fp32 argmin for ambiguous tokens ----------------
// One block per token (grid-stride). fp32 accumulation order matches the known-good
// R6 kernel exactly: even-k / odd-k partial sums, then fmaf(-2, se+so, e2).
__global__ void __launch_bounds__(256, 4)
k_rescan(const float* __restrict__ x, const float* __restrict__ emb,
         float* __restrict__ out_q, float* __restrict__ out_ind)
{
    __shared__ float xs[D];
    __shared__ float rv[8];
    __shared__ int   ri[8];
    __shared__ int   sfin;
    const int tid = threadIdx.x;
    const int n = g_ncand;

    for (int li = blockIdx.x; li < n; li += gridDim.x) {
        int tok = g_list[li];
        if (tid < D) xs[tid] = x[(size_t)tok * D + tid];
        __syncthreads();

        float best = 3.4e38f;
        int   bidx = 0;
#pragma unroll
        for (int j = 0; j < 8; j++) {
            int c = tid * 8 + j;               // per-thread codes ascending
            const float* e = emb + (size_t)c * D;
            float se = 0.0f, so = 0.0f;
#pragma unroll 16
            for (int k = 0; k < D; k += 2) {
                se = fmaf(xs[k],     e[k],     se);
                so = fmaf(xs[k + 1], e[k + 1], so);
            }
            float s = fmaf(-2.0f, se + so, g_e2[c]);
            if (s < best) { best = s; bidx = c; }
        }
        // warp reduce (tie -> lowest index)
#pragma unroll
        for (int off = 16; off; off >>= 1) {
            float ov = __shfl_xor_sync(0xffffffffu, best, off);
            int   oi = __shfl_xor_sync(0xffffffffu, bidx, off);
            if (ov < best || (ov == best && oi < bidx)) { best = ov; bidx = oi; }
        }
        if ((tid & 31) == 0) { rv[tid >> 5] = best; ri[tid >> 5] = bidx; }
        __syncthreads();
        if (tid == 0) {
            float v = rv[0]; int id = ri[0];
#pragma unroll
            for (int w = 1; w < 8; w++)
                if (rv[w] < v || (rv[w] == v && ri[w] < id)) { v = rv[w]; id = ri[w]; }
            sfin = id;
            out_ind[tok] = (float)id;
            atomicAdd(&g_counts[id], 1.0f);
        }
        __syncthreads();
        int fi = sfin;
        if (tid < D) {
            out_q[(size_t)tok * D + tid] = emb[(size_t)fi * D + tid];
            atomicAdd(&g_embed_sum[(size_t)fi * D + tid], xs[tid]);
        }
        __syncthreads();
    }
}

// ---------------- K3: cluster-size EMA + laplace smoothing (single block) ----------------
__global__ void k_cluster(const float* __restrict__ cs, float* __restrict__ out_cs) {
    __shared__ float red[32];
    __shared__ float s_tot;
    int tid = threadIdx.x;  // 1024
    float ncs[2];
    float local = 0.0f;
#pragma unroll
    for (int i = 0; i < 2; i++) {
        int c = tid + i * 1024;
        ncs[i] = cs[c] * DECAY + g_counts[c] * (1.0f - DECAY);
        out_cs[c] = ncs[i];
        local += ncs[i];
    }
#pragma unroll
    for (int o = 16; o; o >>= 1) local += __shfl_xor_sync(0xffffffffu, local, o);
    if ((tid & 31) == 0) red[tid >> 5] = local;
    __syncthreads();
    if (tid < 32) {
        float v = red[tid];
#pragma unroll
        for (int o = 16; o; o >>= 1) v += __shfl_xor_sync(0xffffffffu, v, o);
        if (tid == 0) s_tot = v;
    }
    __syncthreads();
    float tot = s_tot;
#pragma unroll
    for (int i = 0; i < 2; i++) {
        int c = tid + i * 1024;
        g_smooth[c] = (ncs[i] + EPSV) / (tot + (float)C * EPSV) * tot;
    }
}

// ---------------- K4: embed_avg EMA + renormalized embeddings ----------------
__global__ void k_embed(const float* __restrict__ ea,
                        float* __restrict__ out_emb, float* __restrict__ out_ea) {
    int i = blockIdx.x * 256 + threadIdx.x;  // over 32768 float4
    int c = i >> 4;
    float4 e = ((const float4*)ea)[i];
    float4 s = ((const float4*)g_embed_sum)[i];
    float4 na;
    na.x = e.x * DECAY + s.x * (1.0f - DECAY);
    na.y = e.y * DECAY + s.y * (1.0f - DECAY);
    na.z = e.z * DECAY + s.z * (1.0f - DECAY);
    na.w = e.w * DECAY + s.w * (1.0f - DECAY);
    ((float4*)out_ea)[i] = na;
    float sm = g_smooth[c];
    float4 ne;
    ne.x = na.x / sm; ne.y = na.y / sm; ne.z = na.z / sm; ne.w = na.w / sm;
    ((float4*)out_emb)[i] = ne;
}

// ---------------- launch ----------------
extern "C" void kernel_launch(void* const* d_in, const int* in_sizes, int n_in,
                              void* d_out, int out_size) {
    const float* x   = (const float*)d_in[0];
    const float* emb = (const float*)d_in[1];
    const float* cs  = (const float*)d_in[2];
    const float* ea  = (const float*)d_in[3];
    float* out = (float*)d_out;

    float* out_q   = out;
    float* out_ind = out + OFF_IND;
    float* out_emb = out + OFF_EMB;
    float* out_cs  = out + OFF_CS;
    float* out_ea  = out + OFF_EA;

    cudaFuncSetAttribute(k_assign, cudaFuncAttributeMaxDynamicSharedMemorySize, SMEM_ASGN);

    k_prep<<<(C * D + 255) / 256, 256>>>(emb);
    k_assign<<<NT / M_CTA, 256, SMEM_ASGN>>>(x, emb, out_q, out_ind);
    k_rescan<<<512, 256>>>(x, emb, out_q, out_ind);
    k_cluster<<<1, 1024>>>(cs, out_cs);
    k_embed<<<(C * D / 4 + 255) / 256, 256>>>(ea, out_emb, out_ea);
}